// round 1
// baseline (speedup 1.0000x reference)
#include <cuda_runtime.h>
#include <math.h>

#define NBATCH 8
#define DPIX   147456     // 384*384
#define KBINS  512
#define BINS   50
#define B_ROW  514        // odd-parity array row stride
#define B_TOT  (NBATCH*KBINS*B_ROW + 4)   // 2105348, divisible by 4

// Scratch (device globals; no dynamic allocation allowed)
__device__ __align__(16) float g_A[NBATCH * KBINS * KBINS];  // even-j0 histogram (8 MB)
__device__ __align__(16) float g_Braw[B_TOT];                // odd-j0 histogram (+1 float offset)
__device__ __align__(16) float g_G [BINS * KBINS];           // G[b][i]
__device__ __align__(16) float g_GT[KBINS * BINS];           // GT[i][b]
__device__ __align__(16) float g_P [NBATCH * BINS * KBINS];  // P[n][b][j]
__device__ __align__(16) float g_hgram[NBATCH * BINS * BINS];

// ---------------- Kernel 1: zero histograms + precompute soft-bin kernel G ----
__global__ void k_init() {
    int gid = blockIdx.x * blockDim.x + threadIdx.x;
    int stride = gridDim.x * blockDim.x;
    float4 z = make_float4(0.f, 0.f, 0.f, 0.f);
    float4* A4 = (float4*)g_A;
    int totA = (NBATCH * KBINS * KBINS) / 4;
    for (int t = gid; t < totA; t += stride) A4[t] = z;
    float4* B4 = (float4*)g_Braw;
    int totB = B_TOT / 4;
    for (int t = gid; t < totB; t += stride) B4[t] = z;

    for (int t = gid; t < BINS * KBINS; t += stride) {
        int b = t / KBINS, i = t % KBINS;
        double x = (i + 0.5) / (double)KBINS;
        double c = (b + 0.5) * 0.02;
        double d = 10.0 * (x - c);
        double s1 = 1.0 / (1.0 + exp(-(d + 0.1)));
        double s2 = 1.0 / (1.0 + exp(-(d - 0.1)));
        float v = (float)(s1 - s2);
        g_G [b * KBINS + i] = v;
        g_GT[i * BINS  + b] = v;
    }
}

// ---------------- Kernel 2: bilinear 2D histogram with vector REDs ------------
__device__ __forceinline__ void red2(float* p, float a, float b) {
    asm volatile("red.global.add.v2.f32 [%0], {%1, %2};"
                 :: "l"(p), "f"(a), "f"(b) : "memory");
}

__global__ void k_hist(const float* __restrict__ im1, const float* __restrict__ im2) {
    int gid = blockIdx.x * blockDim.x + threadIdx.x;   // one float4 chunk (4 pixels)
    const int nchunk = (NBATCH * DPIX) / 4;
    if (gid >= nchunk) return;
    int n = gid / (DPIX / 4);   // 147456/4 = 36864 chunks per batch, no straddle
    float4 xv = ((const float4*)im1)[gid];
    float4 yv = ((const float4*)im2)[gid];
    size_t baseA = (size_t)n * KBINS * KBINS;
    size_t baseB = (size_t)n * KBINS * B_ROW;

    float xs[4] = {xv.x, xv.y, xv.z, xv.w};
    float ys[4] = {yv.x, yv.y, yv.z, yv.w};
#pragma unroll
    for (int q = 0; q < 4; q++) {
        float u = xs[q] * 512.0f - 0.5f;
        float fi = fminf(510.0f, fmaxf(0.0f, floorf(u)));
        int   i0 = (int)fi;
        float wx = u - fi;
        float v  = ys[q] * 512.0f - 0.5f;
        float fj = fminf(510.0f, fmaxf(0.0f, floorf(v)));
        int   j0 = (int)fj;
        float wy = v - fj;
        float ax = 1.0f - wx, ay = 1.0f - wy;

        bool odd = (j0 & 1);
        float* arr = odd ? (g_Braw + 1 + baseB) : (g_A + baseA);
        int    rs  = odd ? B_ROW : KBINS;
        float* p   = arr + (size_t)i0 * rs + j0;   // 8B-aligned by parity construction
        red2(p,      ax * ay, ax * wy);
        red2(p + rs, wx * ay, wx * wy);
    }
}

// ---------------- Kernel 3: P[n][b][j] = sum_i G[b][i] * H[n][i][j] -----------
// grid = 8(n) * 4(jtile of 128) * 5(b-group of 10) = 160 blocks, 128 threads
__global__ void k_stageC() {
    int blk = blockIdx.x;
    int n  = blk / 20;
    int r  = blk % 20;
    int jt = r / 5, bg = r % 5;
    int j  = jt * 128 + threadIdx.x;
    int b0 = bg * 10;

    __shared__ float Gs[64][12];   // 48B rows -> float4-aligned
    float acc[10];
#pragma unroll
    for (int k = 0; k < 10; k++) acc[k] = 0.0f;

    const float* A = g_A    +      (size_t)n * KBINS * KBINS + j;
    const float* B = g_Braw + 1 +  (size_t)n * KBINS * B_ROW + j;

    for (int it = 0; it < KBINS; it += 64) {
        __syncthreads();
        for (int t = threadIdx.x; t < 640; t += 128) {
            int ii = t / 10, k = t % 10;
            Gs[ii][k] = g_GT[(it + ii) * BINS + b0 + k];
        }
        __syncthreads();
#pragma unroll 8
        for (int ii = 0; ii < 64; ii++) {
            int i = it + ii;
            float h = A[(size_t)i * KBINS] + B[(size_t)i * B_ROW];
            float4 ga = *(const float4*)&Gs[ii][0];
            float4 gb = *(const float4*)&Gs[ii][4];
            float2 gc = *(const float2*)&Gs[ii][8];
            acc[0] += h * ga.x; acc[1] += h * ga.y; acc[2] += h * ga.z; acc[3] += h * ga.w;
            acc[4] += h * gb.x; acc[5] += h * gb.y; acc[6] += h * gb.z; acc[7] += h * gb.w;
            acc[8] += h * gc.x; acc[9] += h * gc.y;
        }
    }
    size_t pb = ((size_t)n * BINS + b0) * KBINS + j;
#pragma unroll
    for (int k = 0; k < 10; k++) g_P[pb + (size_t)k * KBINS] = acc[k];
}

// ---------------- Kernel 4: hgram[n][b][c] = sum_j P[n][b][j] * G[c][j] -------
// grid = 400 (n*50+b), 256 threads
__global__ void k_stageD() {
    int nb = blockIdx.x;
    __shared__ float Ps[KBINS];
    const float* P = g_P + (size_t)nb * KBINS;
    for (int t = threadIdx.x; t < KBINS; t += 256) Ps[t] = P[t];
    __syncthreads();
    int w = threadIdx.x >> 5, lane = threadIdx.x & 31;
    for (int c = w; c < BINS; c += 8) {
        const float* Gc = g_G + (size_t)c * KBINS;
        float s = 0.0f;
#pragma unroll
        for (int q = 0; q < KBINS / 32; q++) {
            int jj = q * 32 + lane;
            s += Ps[jj] * Gc[jj];
        }
#pragma unroll
        for (int o = 16; o; o >>= 1) s += __shfl_xor_sync(0xffffffffu, s, o);
        if (lane == 0) g_hgram[(size_t)nb * BINS + c] = s;
    }
}

// ---------------- Kernel 5: normalize, marginals, MI --------------------------
__global__ void k_stageE(float* __restrict__ out) {
    __shared__ float red[512];
    __shared__ float mx[NBATCH * BINS], my[NBATCH * BINS];
    __shared__ float sS;
    int tid = threadIdx.x;
    const int TOT = NBATCH * BINS * BINS;

    float s = 0.0f;
    for (int t = tid; t < TOT; t += 512) s += g_hgram[t];
    red[tid] = s; __syncthreads();
    for (int o = 256; o; o >>= 1) { if (tid < o) red[tid] += red[tid + o]; __syncthreads(); }
    if (tid == 0) sS = red[0];

    if (tid < NBATCH * BINS) {
        int n = tid / BINS, b = tid % BINS;
        const float* Hn = g_hgram + (size_t)n * BINS * BINS;
        float m1 = 0.0f, m2 = 0.0f;
        for (int c = 0; c < BINS; c++) { m1 += Hn[b * BINS + c]; m2 += Hn[c * BINS + b]; }
        mx[tid] = m1; my[tid] = m2;
    }
    __syncthreads();

    float inv = 1.0f / sS;
    float mi = 0.0f;
    for (int t = tid; t < TOT; t += 512) {
        int n = t / (BINS * BINS);
        int rem = t - n * (BINS * BINS);
        int b = rem / BINS, c = rem % BINS;
        float p = g_hgram[t] * inv;
        float q = (mx[n * BINS + b] * inv) * (my[n * BINS + c] * inv);
        mi += p * (logf(p + 1e-8f) - logf(q + 1e-8f));
    }
    red[tid] = mi; __syncthreads();
    for (int o = 256; o; o >>= 1) { if (tid < o) red[tid] += red[tid + o]; __syncthreads(); }
    if (tid == 0) out[0] = red[0];
}

// ---------------- Launch -------------------------------------------------------
extern "C" void kernel_launch(void* const* d_in, const int* in_sizes, int n_in,
                              void* d_out, int out_size) {
    const float* im1 = (const float*)d_in[0];
    const float* im2 = (const float*)d_in[1];
    k_init  <<<512, 256>>>();
    k_hist  <<<(NBATCH * DPIX / 4 + 255) / 256, 256>>>(im1, im2);
    k_stageC<<<160, 128>>>();
    k_stageD<<<400, 256>>>();
    k_stageE<<<1, 512>>>((float*)d_out);
}

// round 2
// speedup vs baseline: 1.9597x; 1.9597x over previous
#include <cuda_runtime.h>
#include <math.h>

#define NBATCH 8
#define DPIX   147456     // 384*384
#define KBINS  256
#define BINS   50
#define B_ROW  258        // odd-parity array row stride (even, keeps 8B align)
#define B_TOT  (NBATCH*KBINS*B_ROW + 4)   // 528388, divisible by 4

// Scratch (device globals; no dynamic allocation allowed)
__device__ __align__(16) float g_A[NBATCH * KBINS * KBINS];  // even-j0 histogram (2 MB)
__device__ __align__(16) float g_Braw[B_TOT];                // odd-j0 histogram (+1 float offset)
__device__ __align__(16) float g_G [BINS * KBINS];           // G[b][i]
__device__ __align__(16) float g_GT[KBINS * BINS];           // GT[i][b]
__device__ __align__(16) float g_P [2 * NBATCH * BINS * KBINS];  // P halves [is][n][b][j]
__device__ __align__(16) float g_hgram[NBATCH * BINS * BINS];

// ---------------- Kernel 1: zero histograms + precompute soft-bin kernel G ----
__global__ void k_init() {
    int gid = blockIdx.x * blockDim.x + threadIdx.x;
    int stride = gridDim.x * blockDim.x;
    float4 z = make_float4(0.f, 0.f, 0.f, 0.f);
    float4* A4 = (float4*)g_A;
    int totA = (NBATCH * KBINS * KBINS) / 4;
    for (int t = gid; t < totA; t += stride) A4[t] = z;
    float4* B4 = (float4*)g_Braw;
    int totB = B_TOT / 4;
    for (int t = gid; t < totB; t += stride) B4[t] = z;

    for (int t = gid; t < BINS * KBINS; t += stride) {
        int b = t / KBINS, i = t % KBINS;
        double x = (i + 0.5) / (double)KBINS;
        double c = (b + 0.5) * 0.02;
        double d = 10.0 * (x - c);
        double s1 = 1.0 / (1.0 + exp(-(d + 0.1)));
        double s2 = 1.0 / (1.0 + exp(-(d - 0.1)));
        float v = (float)(s1 - s2);
        g_G [b * KBINS + i] = v;
        g_GT[i * BINS  + b] = v;
    }
}

// ---------------- Kernel 2: bilinear 2D histogram with vector REDs ------------
__device__ __forceinline__ void red2(float* p, float a, float b) {
    asm volatile("red.global.add.v2.f32 [%0], {%1, %2};"
                 :: "l"(p), "f"(a), "f"(b) : "memory");
}

__global__ void k_hist(const float* __restrict__ im1, const float* __restrict__ im2) {
    int gid = blockIdx.x * blockDim.x + threadIdx.x;   // one float4 chunk (4 pixels)
    const int nchunk = (NBATCH * DPIX) / 4;
    if (gid >= nchunk) return;
    int n = gid / (DPIX / 4);   // 36864 chunks per batch, no straddle
    float4 xv = ((const float4*)im1)[gid];
    float4 yv = ((const float4*)im2)[gid];
    size_t baseA = (size_t)n * KBINS * KBINS;
    size_t baseB = (size_t)n * KBINS * B_ROW;

    float xs[4] = {xv.x, xv.y, xv.z, xv.w};
    float ys[4] = {yv.x, yv.y, yv.z, yv.w};
#pragma unroll
    for (int q = 0; q < 4; q++) {
        float u = xs[q] * 256.0f - 0.5f;
        float fi = fminf(254.0f, fmaxf(0.0f, floorf(u)));
        int   i0 = (int)fi;
        float wx = u - fi;
        float v  = ys[q] * 256.0f - 0.5f;
        float fj = fminf(254.0f, fmaxf(0.0f, floorf(v)));
        int   j0 = (int)fj;
        float wy = v - fj;
        float ax = 1.0f - wx, ay = 1.0f - wy;

        bool odd = (j0 & 1);
        float* arr = odd ? (g_Braw + 1 + baseB) : (g_A + baseA);
        int    rs  = odd ? B_ROW : KBINS;
        float* p   = arr + (size_t)i0 * rs + j0;   // 8B-aligned by parity construction
        red2(p,      ax * ay, ax * wy);
        red2(p + rs, wx * ay, wx * wy);
    }
}

// ---------------- Kernel 3: P[is][n][b][j] = sum_{i in half} G[b][i]*H[n][i][j]
// grid = 8(n) * 2(jtile of 128) * 5(b-group of 10) * 2(i-half) = 160 blocks, 128 threads
__global__ void k_stageC() {
    int blk = blockIdx.x;
    int n  = blk / 20;
    int r  = blk % 20;
    int jt = r / 10;
    int r2 = r % 10;
    int bg = r2 / 2, is = r2 % 2;
    int j  = jt * 128 + threadIdx.x;
    int b0 = bg * 10;
    int i_beg = is * 128;

    __shared__ float Gs[64][12];   // 48B rows -> float4-aligned
    float acc[10];
#pragma unroll
    for (int k = 0; k < 10; k++) acc[k] = 0.0f;

    const float* A = g_A    +      (size_t)n * KBINS * KBINS + j;
    const float* B = g_Braw + 1 +  (size_t)n * KBINS * B_ROW + j;

    for (int it = i_beg; it < i_beg + 128; it += 64) {
        __syncthreads();
        for (int t = threadIdx.x; t < 640; t += 128) {
            int ii = t / 10, k = t % 10;
            Gs[ii][k] = g_GT[(it + ii) * BINS + b0 + k];
        }
        __syncthreads();
#pragma unroll 8
        for (int ii = 0; ii < 64; ii++) {
            int i = it + ii;
            float h = A[(size_t)i * KBINS] + B[(size_t)i * B_ROW];
            float4 ga = *(const float4*)&Gs[ii][0];
            float4 gb = *(const float4*)&Gs[ii][4];
            float2 gc = *(const float2*)&Gs[ii][8];
            acc[0] += h * ga.x; acc[1] += h * ga.y; acc[2] += h * ga.z; acc[3] += h * ga.w;
            acc[4] += h * gb.x; acc[5] += h * gb.y; acc[6] += h * gb.z; acc[7] += h * gb.w;
            acc[8] += h * gc.x; acc[9] += h * gc.y;
        }
    }
    size_t pb = (((size_t)is * NBATCH + n) * BINS + b0) * KBINS + j;
#pragma unroll
    for (int k = 0; k < 10; k++) g_P[pb + (size_t)k * KBINS] = acc[k];
}

// ---------------- Kernel 4: hgram[n][b][c] = sum_j (P0+P1)[n][b][j] * G[c][j] -
// grid = 400 (n*50+b), 256 threads
__global__ void k_stageD() {
    int nb = blockIdx.x;
    __shared__ float Ps[KBINS];
    const float* P0 = g_P + (size_t)nb * KBINS;
    const float* P1 = g_P + (size_t)(NBATCH * BINS + nb) * KBINS;
    for (int t = threadIdx.x; t < KBINS; t += 256) Ps[t] = P0[t] + P1[t];
    __syncthreads();
    int w = threadIdx.x >> 5, lane = threadIdx.x & 31;
    for (int c = w; c < BINS; c += 8) {
        const float* Gc = g_G + (size_t)c * KBINS;
        float s0 = 0.0f, s1 = 0.0f;
#pragma unroll
        for (int q = 0; q < KBINS / 64; q++) {
            int jj = q * 64 + lane;
            s0 += Ps[jj]      * Gc[jj];
            s1 += Ps[jj + 32] * Gc[jj + 32];
        }
        float s = s0 + s1;
#pragma unroll
        for (int o = 16; o; o >>= 1) s += __shfl_xor_sync(0xffffffffu, s, o);
        if (lane == 0) g_hgram[(size_t)nb * BINS + c] = s;
    }
}

// ---------------- Kernel 5: normalize, marginals, MI --------------------------
__global__ void k_stageE(float* __restrict__ out) {
    __shared__ float red[512];
    __shared__ float mx[NBATCH * BINS], my[NBATCH * BINS];
    __shared__ float sS;
    int tid = threadIdx.x;
    const int TOT = NBATCH * BINS * BINS;

    float s = 0.0f;
    for (int t = tid; t < TOT; t += 512) s += g_hgram[t];
    red[tid] = s; __syncthreads();
    for (int o = 256; o; o >>= 1) { if (tid < o) red[tid] += red[tid + o]; __syncthreads(); }
    if (tid == 0) sS = red[0];

    if (tid < NBATCH * BINS) {
        int n = tid / BINS, b = tid % BINS;
        const float* Hn = g_hgram + (size_t)n * BINS * BINS;
        float m1 = 0.0f, m2 = 0.0f;
        for (int c = 0; c < BINS; c++) { m1 += Hn[b * BINS + c]; m2 += Hn[c * BINS + b]; }
        mx[tid] = m1; my[tid] = m2;
    }
    __syncthreads();

    float inv = 1.0f / sS;
    float mi = 0.0f;
    for (int t = tid; t < TOT; t += 512) {
        int n = t / (BINS * BINS);
        int rem = t - n * (BINS * BINS);
        int b = rem / BINS, c = rem % BINS;
        float p = g_hgram[t] * inv;
        float q = (mx[n * BINS + b] * inv) * (my[n * BINS + c] * inv);
        mi += p * (logf(p + 1e-8f) - logf(q + 1e-8f));
    }
    red[tid] = mi; __syncthreads();
    for (int o = 256; o; o >>= 1) { if (tid < o) red[tid] += red[tid + o]; __syncthreads(); }
    if (tid == 0) out[0] = red[0];
}

// ---------------- Launch -------------------------------------------------------
extern "C" void kernel_launch(void* const* d_in, const int* in_sizes, int n_in,
                              void* d_out, int out_size) {
    const float* im1 = (const float*)d_in[0];
    const float* im2 = (const float*)d_in[1];
    k_init  <<<512, 256>>>();
    k_hist  <<<(NBATCH * DPIX / 4 + 255) / 256, 256>>>(im1, im2);
    k_stageC<<<160, 128>>>();
    k_stageD<<<400, 256>>>();
    k_stageE<<<1, 512>>>((float*)d_out);
}